// round 16
// baseline (speedup 1.0000x reference)
#include <cuda_runtime.h>
#include <cuda_fp16.h>
#include <math.h>
#include <stdint.h>

// ---------------- problem constants ----------------
constexpr int B_ = 2;
constexpr int S_ = 2048;
constexpr int D_ = 1024;
constexpr int H_ = 16;
constexpr int HD_ = 64;
constexpr int M_ = B_ * S_;          // 4096 rows
constexpr float LN_EPS = 1e-5f;
constexpr int BM_WORDS = M_ * S_ / 32;

// ---------------- device scratch (no allocations allowed) ----------------
__device__ float g_h2 [M_ * D_];
__device__ float g_qkvb[3 * D_];

constexpr size_t WT_ELEMS = 24ull * 1024 * 1024;
__device__ __half g_wt  [WT_ELEMS];                 // transposed fp16 weights
__device__ __half g_a_hi[M_ * 4 * D_];
__device__ __half g_a_lo[M_ * 4 * D_];
__device__ __half g_b_hi[M_ * 4 * D_];
__device__ __half g_b_lo[M_ * 4 * D_];
__device__ __half g_qhi[M_ * D_], g_qlo[M_ * D_];
__device__ __half g_khi[M_ * D_];
__device__ __half g_vhi[M_ * D_];
__device__ __half g_yhi[M_ * D_], g_ylo[M_ * D_];   // y split (prep-time)
__device__ uint32_t g_bms[BM_WORDS];
__device__ uint32_t g_bmc[BM_WORDS];

// ---------------- PTX helpers (sm_80-class only) ----------------
__device__ __forceinline__ uint32_t smem_to_u32(const void* smem_ptr) {
    uint32_t addr;
    asm("{ .reg .u64 tmp; cvta.to.shared.u64 tmp, %1; cvt.u32.u64 %0, tmp; }"
        : "=r"(addr) : "l"(smem_ptr));
    return addr;
}
#define CP_ASYNC16(dst_u32, src_ptr) \
    asm volatile("cp.async.cg.shared.global [%0], [%1], 16;" \
        :: "r"(dst_u32), "l"(src_ptr))
#define CP_COMMIT() asm volatile("cp.async.commit_group;" ::: "memory")
#define CP_WAIT0()  asm volatile("cp.async.wait_group 0;" ::: "memory")
#define CP_WAIT1()  asm volatile("cp.async.wait_group 1;" ::: "memory")
#define CP_WAIT2()  asm volatile("cp.async.wait_group 2;" ::: "memory")

#define LDSM_X4(r0, r1, r2, r3, addr) \
    asm volatile("ldmatrix.sync.aligned.m8n8.x4.shared.b16 {%0,%1,%2,%3}, [%4];" \
        : "=r"(r0), "=r"(r1), "=r"(r2), "=r"(r3) : "r"(addr))
#define LDSM_X4_T(r0, r1, r2, r3, addr) \
    asm volatile("ldmatrix.sync.aligned.m8n8.x4.trans.shared.b16 {%0,%1,%2,%3}, [%4];" \
        : "=r"(r0), "=r"(r1), "=r"(r2), "=r"(r3) : "r"(addr))

#define MMA_F16(c0, c1, c2, c3, a0, a1, a2, a3, b0, b1) \
    asm volatile("mma.sync.aligned.m16n8k16.row.col.f32.f16.f16.f32 " \
        "{%0,%1,%2,%3}, {%4,%5,%6,%7}, {%8,%9}, {%0,%1,%2,%3};" \
        : "+f"(c0), "+f"(c1), "+f"(c2), "+f"(c3) \
        : "r"(a0), "r"(a1), "r"(a2), "r"(a3), "r"(b0), "r"(b1))

__device__ __forceinline__ uint32_t h2u(__half2 v) {
    return *reinterpret_cast<uint32_t*>(&v);
}

// segmented-output descriptor: column segment s (1024 cols) -> hi[s]/lo[s]
struct SegOut { __half* hi[3]; __half* lo[3]; };

__device__ __forceinline__ uint32_t swz(uint32_t row, uint32_t gk) {
    return row * 64u + ((gk ^ ((row >> 1) & 3u)) << 4);
}

// ============================================================
// HMMA fp16 GEMM: C = (Ah[+Al])[M,K] @ Wh[N,K]^T  (terms = 1 or 2)
// CTA 128x128, BK=32, 8 warps, 4-stage cp.async, 2 CTAs/SM.
// Single barrier per k-tile (proven geometry).
// outmode 0: fp32 Cf; 1: hi(/lo) Chi/Clo; 3: segmented SegOut
// ============================================================
constexpr int TILEB   = 8192;
constexpr int STAGEB  = 3 * TILEB;           // Ah, Al, Wh = 24KB
constexpr int GEMM_SMEM = 4 * STAGEB;        // 98304 (2 CTAs -> 192KB)

__global__ __launch_bounds__(256, 2)
void mma_gemm_kernel(const __half* __restrict__ Ahi, const __half* __restrict__ Alo,
                     const __half* __restrict__ Wh,
                     const float* __restrict__ bias, float* __restrict__ Cf,
                     __half* __restrict__ Chi, __half* __restrict__ Clo,
                     SegOut so,
                     int M, int N, int K, int relu, int outmode, int terms)
{
    extern __shared__ char smem[];
    const uint32_t su = smem_to_u32(smem);
    const int tid  = threadIdx.x;
    const int wid  = tid >> 5;
    const int lane = tid & 31;
    const int block_row = blockIdx.y * 128;
    const int block_col = blockIdx.x * 128;

    const __half* basep[3] = { Ahi, Alo, Wh };
    const int rowoff[3] = { block_row, block_row, block_col };

    auto load_stage = [&](int p, int kt) {
        const int k0 = kt * 32;
        #pragma unroll
        for (int i = 0; i < 6; i++) {
            int lin  = tid + (i << 8);
            int tile = lin >> 9;
            if (terms == 1 && tile == 1) continue;     // skip Alo tile
            int rem  = lin & 511;
            int row  = rem >> 2;
            int g    = rem & 3;
            const __half* src =
                basep[tile] + (size_t)(rowoff[tile] + row) * K + k0 + g * 8;
            uint32_t dst = su + p * STAGEB + tile * TILEB + swz(row, g);
            CP_ASYNC16(dst, src);
        }
    };

    float c[2][8][4];
    #pragma unroll
    for (int s = 0; s < 2; s++)
        #pragma unroll
        for (int n = 0; n < 8; n++)
            #pragma unroll
            for (int i = 0; i < 4; i++) c[s][n][i] = 0.f;

    const int wm = (wid & 3) * 32;
    const int wn = (wid >> 2) * 64;

    const int a_row  = (lane & 15);
    const int a_gsel = (lane >> 4);
    const int b_noff = ((lane >> 4) << 3) + (lane & 7);
    const int b_gsel = (lane >> 3) & 1;

    const int KT = K >> 5;
    load_stage(0, 0); CP_COMMIT();
    load_stage(1, 1); CP_COMMIT();
    load_stage(2, 2); CP_COMMIT();

    for (int kt = 0; kt < KT; kt++) {
        const int ahead = KT - 1 - kt;
        if (ahead >= 2)      CP_WAIT2();
        else if (ahead == 1) CP_WAIT1();
        else                 CP_WAIT0();
        __syncthreads();
        if (kt + 3 < KT) { load_stage((kt + 3) & 3, kt + 3); CP_COMMIT(); }

        const uint32_t stAhi = su + (kt & 3) * STAGEB;
        const uint32_t stAlo = stAhi + TILEB;
        const uint32_t stWh  = stAhi + 2 * TILEB;

        #pragma unroll
        for (int kk = 0; kk < 2; kk++) {
            uint32_t ah[2][4], al[2][4], bh[8][2];
            #pragma unroll
            for (int s = 0; s < 2; s++) {
                uint32_t ro = (uint32_t)(wm + s * 16 + a_row);
                uint32_t gk = (uint32_t)(kk * 2 + a_gsel);
                LDSM_X4(ah[s][0], ah[s][1], ah[s][2], ah[s][3], stAhi + swz(ro, gk));
                if (terms == 2)
                    LDSM_X4(al[s][0], al[s][1], al[s][2], al[s][3], stAlo + swz(ro, gk));
            }
            #pragma unroll
            for (int grp = 0; grp < 4; grp++) {
                uint32_t ro = (uint32_t)(wn + grp * 16 + b_noff);
                uint32_t gk = (uint32_t)(kk * 2 + b_gsel);
                LDSM_X4(bh[2*grp][0], bh[2*grp][1], bh[2*grp+1][0], bh[2*grp+1][1],
                        stWh + swz(ro, gk));
            }
            #pragma unroll
            for (int s = 0; s < 2; s++)
                #pragma unroll
                for (int n = 0; n < 8; n++)
                    MMA_F16(c[s][n][0], c[s][n][1], c[s][n][2], c[s][n][3],
                            ah[s][0], ah[s][1], ah[s][2], ah[s][3],
                            bh[n][0], bh[n][1]);
            if (terms == 2) {
                #pragma unroll
                for (int s = 0; s < 2; s++)
                    #pragma unroll
                    for (int n = 0; n < 8; n++)
                        MMA_F16(c[s][n][0], c[s][n][1], c[s][n][2], c[s][n][3],
                                al[s][0], al[s][1], al[s][2], al[s][3],
                                bh[n][0], bh[n][1]);
            }
        }
    }

    // segment routing (uniform per CTA: 1024 % 128 == 0)
    const int seg = block_col >> 10;
    __half* seg_hi = (outmode == 3) ? so.hi[seg] : Chi;
    __half* seg_lo = (outmode == 3) ? so.lo[seg] : Clo;
    const int cstride = (outmode == 3) ? D_ : N;
    const int cmask = (outmode == 3) ? 1023 : 0x7fffffff;

    const int gp  = lane >> 2;
    const int tig = lane & 3;
    #pragma unroll
    for (int s = 0; s < 2; s++) {
        const int r0 = block_row + wm + s * 16 + gp;
        #pragma unroll
        for (int n = 0; n < 8; n++) {
            const int col = block_col + wn + n * 8 + tig * 2;
            float b0 = bias ? __ldg(&bias[col])     : 0.f;
            float b1 = bias ? __ldg(&bias[col + 1]) : 0.f;
            float v0 = c[s][n][0] + b0, v1 = c[s][n][1] + b1;
            float v2 = c[s][n][2] + b0, v3 = c[s][n][3] + b1;
            if (relu) {
                v0 = fmaxf(v0, 0.f); v1 = fmaxf(v1, 0.f);
                v2 = fmaxf(v2, 0.f); v3 = fmaxf(v3, 0.f);
            }
            if (outmode == 0) {
                *(float2*)&Cf[(size_t)r0 * N + col]       = make_float2(v0, v1);
                *(float2*)&Cf[(size_t)(r0 + 8) * N + col] = make_float2(v2, v3);
            } else {
                const int lc = col & cmask;
                __half2 h01 = __float22half2_rn(make_float2(v0, v1));
                __half2 h23 = __float22half2_rn(make_float2(v2, v3));
                *(__half2*)&seg_hi[(size_t)r0 * cstride + lc]       = h01;
                *(__half2*)&seg_hi[(size_t)(r0 + 8) * cstride + lc] = h23;
                if (seg_lo) {
                    __half2 l01 = __float22half2_rn(make_float2(
                        v0 - __half2float(h01.x), v1 - __half2float(h01.y)));
                    __half2 l23 = __float22half2_rn(make_float2(
                        v2 - __half2float(h23.x), v3 - __half2float(h23.y)));
                    *(__half2*)&seg_lo[(size_t)r0 * cstride + lc]       = l01;
                    *(__half2*)&seg_lo[(size_t)(r0 + 8) * cstride + lc] = l23;
                }
            }
        }
    }
}

// ============================================================
// MMA flash attention (fp16). QK: 2-term. PV: 1-term. Output hi
// only. CTA: 64 q-rows, 4 warps, Bc=64, bitmap mask, triple-buffer.
// ============================================================
constexpr int ATT_STAGE = 16384;
constexpr int ATT_SMEM  = 3 * ATT_STAGE;     // 49152

__device__ __forceinline__ uint32_t offKV(uint32_t row, uint32_t g) {
    return row * 128u + ((g ^ (row & 7u)) << 4);
}

__global__ __launch_bounds__(128, 4)
void mma_attn_kernel(const __half* __restrict__ Qhi, const __half* __restrict__ Qlo,
                     const __half* __restrict__ Khi, const __half* __restrict__ Vhi,
                     const uint32_t* __restrict__ bm,
                     __half* __restrict__ Ohi,
                     int selfmode)
{
    extern __shared__ char smem[];
    const uint32_t su = smem_to_u32(smem);
    const int tid = threadIdx.x, wid = tid >> 5, lane = tid & 31;
    const int b = blockIdx.x >> 4, h = blockIdx.x & 15;
    const int q0 = blockIdx.y * 64;

    #pragma unroll
    for (int i = 0; i < 8; i++) {
        int lin = tid + (i << 7);
        int t = lin >> 9, rem = lin & 511, row = rem >> 3, g = rem & 7;
        const __half* src = (t ? Qlo : Qhi) +
            ((size_t)b * S_ + q0 + row) * D_ + h * 64 + g * 8;
        CP_ASYNC16(su + t * 8192 + offKV(row, g), src);
    }
    CP_COMMIT(); CP_WAIT0(); __syncthreads();

    uint32_t qa_hi[4][4], qa_lo[4][4];
    {
        const uint32_t arow = (uint32_t)(wid * 16 + (lane & 15));
        const uint32_t ag = (uint32_t)(lane >> 4);
        #pragma unroll
        for (int kk = 0; kk < 4; kk++) {
            LDSM_X4(qa_hi[kk][0], qa_hi[kk][1], qa_hi[kk][2], qa_hi[kk][3],
                    su + offKV(arow, kk * 2 + ag));
            LDSM_X4(qa_lo[kk][0], qa_lo[kk][1], qa_lo[kk][2], qa_lo[kk][3],
                    su + 8192 + offKV(arow, kk * 2 + ag));
        }
    }
    __syncthreads();

    float o[8][4];
    #pragma unroll
    for (int n = 0; n < 8; n++)
        #pragma unroll
        for (int i = 0; i < 4; i++) o[n][i] = 0.f;
    float m0 = -INFINITY, m1 = -INFINITY, l0 = 0.f, l1 = 0.f;
    const float scale = 0.125f;
    const float bigneg = selfmode ? -3.0e38f : -1.25e8f;

    const int b_noff = ((lane >> 4) << 3) + (lane & 7);
    const int b_gsel = (lane >> 3) & 1;
    const int mr0 = wid * 16 + (lane >> 2);
    const int msh = (2 * (lane & 3));

    const __half* kvp[2] = { Khi, Vhi };
    const uint32_t* bmr0 = bm + ((size_t)b * S_ + q0 + mr0) * (S_ / 32);
    const uint32_t* bmr1 = bmr0 + 8 * (S_ / 32);

    auto load_kv = [&](int buf, int jt) {
        const int j0 = jt * 64;
        #pragma unroll
        for (int i = 0; i < 8; i++) {
            int lin = tid + (i << 7);
            int t = lin >> 9, rem = lin & 511, row = rem >> 3, g = rem & 7;
            CP_ASYNC16(su + buf * ATT_STAGE + t * 8192 + offKV(row, g),
                       kvp[t] + ((size_t)b * S_ + j0 + row) * D_ + h * 64 + g * 8);
        }
    };

    load_kv(0, 0); CP_COMMIT();
    load_kv(1, 1); CP_COMMIT();

    int buf = 0;
    for (int jt = 0; jt < 32; jt++) {
        const int ahead = 31 - jt;
        if (ahead >= 1) CP_WAIT1();
        else            CP_WAIT0();
        __syncthreads();
        if (jt + 2 < 32) {
            int nb = buf + 2; if (nb >= 3) nb -= 3;
            load_kv(nb, jt + 2); CP_COMMIT();
        }

        const uint32_t sb = su + buf * ATT_STAGE;
        buf++; if (buf == 3) buf = 0;

        const uint32_t u00 = __ldg(&bmr0[jt * 2]), u01 = __ldg(&bmr0[jt * 2 + 1]);
        const uint32_t u10 = __ldg(&bmr1[jt * 2]), u11 = __ldg(&bmr1[jt * 2 + 1]);

        float sc[8][4];
        #pragma unroll
        for (int n = 0; n < 8; n++)
            #pragma unroll
            for (int i = 0; i < 4; i++) sc[n][i] = 0.f;

        #pragma unroll
        for (int kk = 0; kk < 4; kk++) {
            uint32_t kbh[8][2];
            #pragma unroll
            for (int grp = 0; grp < 4; grp++) {
                uint32_t ro = (uint32_t)(grp * 16 + b_noff);
                uint32_t gd = (uint32_t)(kk * 2 + b_gsel);
                LDSM_X4(kbh[2*grp][0], kbh[2*grp][1], kbh[2*grp+1][0], kbh[2*grp+1][1],
                        sb + offKV(ro, gd));
            }
            #pragma unroll
            for (int n = 0; n < 8; n++)
                MMA_F16(sc[n][0], sc[n][1], sc[n][2], sc[n][3],
                        qa_hi[kk][0], qa_hi[kk][1], qa_hi[kk][2], qa_hi[kk][3],
                        kbh[n][0], kbh[n][1]);
            #pragma unroll
            for (int n = 0; n < 8; n++)
                MMA_F16(sc[n][0], sc[n][1], sc[n][2], sc[n][3],
                        qa_lo[kk][0], qa_lo[kk][1], qa_lo[kk][2], qa_lo[kk][3],
                        kbh[n][0], kbh[n][1]);
        }

        #pragma unroll
        for (int n = 0; n < 8; n++) {
            const uint32_t w0 = (n < 4) ? u00 : u01;
            const uint32_t w1 = (n < 4) ? u10 : u11;
            const int sh = ((n * 8) & 31) + msh;
            bool f0 = (w0 >> sh) & 1, f1 = (w0 >> (sh + 1)) & 1;
            bool f2 = (w1 >> sh) & 1, f3 = (w1 >> (sh + 1)) & 1;
            sc[n][0] = f0 ? bigneg : sc[n][0] * scale;
            sc[n][1] = f1 ? bigneg : sc[n][1] * scale;
            sc[n][2] = f2 ? bigneg : sc[n][2] * scale;
            sc[n][3] = f3 ? bigneg : sc[n][3] * scale;
        }

        float tm0 = -INFINITY, tm1 = -INFINITY;
        #pragma unroll
        for (int n = 0; n < 8; n++) {
            tm0 = fmaxf(tm0, fmaxf(sc[n][0], sc[n][1]));
            tm1 = fmaxf(tm1, fmaxf(sc[n][2], sc[n][3]));
        }
        tm0 = fmaxf(tm0, __shfl_xor_sync(0xffffffffu, tm0, 1));
        tm0 = fmaxf(tm0, __shfl_xor_sync(0xffffffffu, tm0, 2));
        tm1 = fmaxf(tm1, __shfl_xor_sync(0xffffffffu, tm1, 1));
        tm1 = fmaxf(tm1, __shfl_xor_sync(0xffffffffu, tm1, 2));
        float nm0 = fmaxf(m0, tm0), nm1 = fmaxf(m1, tm1);
        float c0 = __expf(m0 - nm0), c1 = __expf(m1 - nm1);
        m0 = nm0; m1 = nm1;

        float rs0 = 0.f, rs1 = 0.f;
        uint32_t pah[8][2];
        #pragma unroll
        for (int n = 0; n < 8; n++) {
            float p0 = __expf(sc[n][0] - m0);
            float p1 = __expf(sc[n][1] - m0);
            float p2 = __expf(sc[n][2] - m1);
            float p3 = __expf(sc[n][3] - m1);
            rs0 += p0 + p1; rs1 += p2 + p3;
            pah[n][0] = h2u(__float22half2_rn(make_float2(p0, p1)));
            pah[n][1] = h2u(__float22half2_rn(make_float2(p2, p3)));
        }
        rs0 += __shfl_xor_sync(0xffffffffu, rs0, 1);
        rs0 += __shfl_xor_sync(0xffffffffu, rs0, 2);
        rs1 += __shfl_xor_sync(0xffffffffu, rs1, 1);
        rs1 += __shfl_xor_sync(0xffffffffu, rs1, 2);
        l0 = l0 * c0 + rs0;
        l1 = l1 * c1 + rs1;
        #pragma unroll
        for (int n = 0; n < 8; n++) {
            o[n][0] *= c0; o[n][1] *= c0; o[n][2] *= c1; o[n][3] *= c1;
        }

        #pragma unroll
        for (int kk = 0; kk < 4; kk++) {
            uint32_t ah0 = pah[2*kk][0], ah1 = pah[2*kk][1];
            uint32_t ah2 = pah[2*kk+1][0], ah3 = pah[2*kk+1][1];
            uint32_t vrow = (uint32_t)(kk * 16 + (lane & 15));
            #pragma unroll
            for (int nbp = 0; nbp < 4; nbp++) {
                uint32_t vg = (uint32_t)(nbp * 2 + (lane >> 4));
                uint32_t vh0, vh1, vh2, vh3;
                LDSM_X4_T(vh0, vh1, vh2, vh3, sb + 8192 + offKV(vrow, vg));
                MMA_F16(o[2*nbp][0], o[2*nbp][1], o[2*nbp][2], o[2*nbp][3],
                        ah0, ah1, ah2, ah3, vh0, vh1);
                MMA_F16(o[2*nbp+1][0], o[2*nbp+1][1], o[2*nbp+1][2], o[2*nbp+1][3],
                        ah0, ah1, ah2, ah3, vh2, vh3);
            }
        }
    }

    const float i0 = 1.f / l0, i1 = 1.f / l1;
    const size_t gr0 = (size_t)b * S_ + q0 + wid * 16 + (lane >> 2);
    #pragma unroll
    for (int n = 0; n < 8; n++) {
        const int col = h * 64 + n * 8 + 2 * (lane & 3);
        __half2 h01 = __float22half2_rn(make_float2(o[n][0] * i0, o[n][1] * i0));
        __half2 h23 = __float22half2_rn(make_float2(o[n][2] * i1, o[n][3] * i1));
        *(__half2*)&Ohi[gr0 * D_ + col]       = h01;
        *(__half2*)&Ohi[(gr0 + 8) * D_ + col] = h23;
    }
}

// ============================================================
// unified prep kernel: ALL weight transposes + mask bitmaps +
// x/y activation splits + bias pack, one flat grid.
// blocks: [0,12288) wsplit; [12288,13312) mprep;
//         [13312,17408) asplit x; [17408,21504) asplit y;
//         [21504,21516) biasprep.   total 21516
// ============================================================
struct PrepAll {
    const float* wsrc[12]; __half* wdst[12];
    const int* mask; uint32_t* bms; uint32_t* bmc;
    const float* x; __half* xhi; __half* xlo;
    const float* y; __half* yhi; __half* ylo;
    const float* qb; const float* kb; const float* vb; float* qkvb;
};

__device__ __forceinline__ void asplit_elem(const float* A, __half* hi, __half* lo, int i)
{
    float4 v = ((const float4*)A)[i];
    __half2 h01 = __float22half2_rn(make_float2(v.x, v.y));
    __half2 h23 = __float22half2_rn(make_float2(v.z, v.w));
    __half2 l01 = __float22half2_rn(make_float2(
        v.x - __half2float(h01.x), v.y - __half2float(h01.y)));
    __half2 l23 = __float22half2_rn(make_float2(
        v.z - __half2float(h23.x), v.w - __half2float(h23.y)));
    ((__half2*)hi)[2 * i + 0] = h01;
    ((__half2*)hi)[2 * i + 1] = h23;
    ((__half2*)lo)[2 * i + 0] = l01;
    ((__half2*)lo)[2 * i + 1] = l23;
}

__global__ __launch_bounds__(256)
void prep_all_kernel(PrepAll p)
{
    __shared__ float t[64][33];
    const int bx = blockIdx.x;
    const int tid = threadIdx.x;

    if (bx < 12288) {
        // ---- weight transpose + fp16 convert ----
        int w, ntile, ktile, K, N;
        if (bx < 4096) {
            w = bx >> 9;
            int r = bx & 511;
            ntile = r & 31; ktile = r >> 5;
            K = 1024; N = 1024;
        } else if (bx < 8192) {
            int i = bx - 4096;
            w = 8 + (i >> 11);
            int r = i & 2047;
            ntile = r & 127; ktile = r >> 7;
            K = 1024; N = 4096;
        } else {
            int i = bx - 8192;
            w = 10 + (i >> 11);
            int r = i & 2047;
            ntile = r & 31; ktile = r >> 5;
            K = 4096; N = 1024;
        }
        const float* W = p.wsrc[w];
        __half* dst = p.wdst[w];
        const int n0 = ntile * 32, k0 = ktile * 64;
        #pragma unroll
        for (int i = 0; i < 8; i++) {
            int lin = tid + (i << 8);
            int kl = lin >> 5, nl = lin & 31;
            t[kl][nl] = W[(size_t)(k0 + kl) * N + n0 + nl];
        }
        __syncthreads();
        #pragma unroll
        for (int i = 0; i < 4; i++) {
            int lin = tid + (i << 8);
            int nr = lin >> 5, kc = lin & 31;
            __half2 v = __float22half2_rn(make_float2(t[2*kc][nr], t[2*kc+1][nr]));
            *(__half2*)&dst[(size_t)(n0 + nr) * K + k0 + 2*kc] = v;
        }
    } else if (bx < 13312) {
        // ---- mask -> bitmaps ----
        const int lane = tid & 31;
        const size_t w = ((size_t)(bx - 12288) * 256 + tid) >> 5;
        const size_t base = w * 1024;
        #pragma unroll 4
        for (int i = 0; i < 32; i++) {
            int mv = p.mask[base + i * 32 + lane];
            uint32_t s = __ballot_sync(0xffffffffu, mv == 1);
            uint32_t c = __ballot_sync(0xffffffffu, mv != 0);
            if (lane == 0) { p.bms[w * 32 + i] = s; p.bmc[w * 32 + i] = c; }
        }
    } else if (bx < 17408) {
        // ---- asplit x ----
        int i = (bx - 13312) * 256 + tid;
        asplit_elem(p.x, p.xhi, p.xlo, i);
    } else if (bx < 21504) {
        // ---- asplit y ----
        int i = (bx - 17408) * 256 + tid;
        asplit_elem(p.y, p.yhi, p.ylo, i);
    } else {
        // ---- bias pack ----
        int i = (bx - 21504) * 256 + tid;
        if (i < 3 * D_)
            p.qkvb[i] = (i < D_) ? p.qb[i]
                       : (i < 2 * D_ ? p.kb[i - D_] : p.vb[i - 2 * D_]);
    }
}

// ============================================================
// LayerNorm
// ============================================================
__global__ __launch_bounds__(256)
void layernorm_kernel(const float* __restrict__ X, const float* __restrict__ gm,
                      const float* __restrict__ bt, float* __restrict__ Yf,
                      __half* __restrict__ Yhi, __half* __restrict__ Ylo,
                      int outmode)
{
    const int row = blockIdx.x;
    const int t = threadIdx.x;
    const float* x = X + (size_t)row * D_;

    float4 xv = *(const float4*)&x[t * 4];
    float s  = xv.x + xv.y + xv.z + xv.w;
    float ss = xv.x * xv.x + xv.y * xv.y + xv.z * xv.z + xv.w * xv.w;

    #pragma unroll
    for (int off = 16; off > 0; off >>= 1) {
        s  += __shfl_xor_sync(0xffffffffu, s, off);
        ss += __shfl_xor_sync(0xffffffffu, ss, off);
    }
    __shared__ float sbuf[8], ssbuf[8];
    if ((t & 31) == 0) { sbuf[t >> 5] = s; ssbuf[t >> 5] = ss; }
    __syncthreads();
    float ts = 0.f, tss = 0.f;
    #pragma unroll
    for (int i = 0; i < 8; i++) { ts += sbuf[i]; tss += ssbuf[i]; }

    const float invD = 1.f / (float)D_;
    float mu  = ts * invD;
    float var = tss * invD - mu * mu;
    float inv = rsqrtf(var + LN_EPS);

    float4 gv = *(const float4*)&gm[t * 4];
    float4 bv = *(const float4*)&bt[t * 4];
    float o0 = (xv.x - mu) * inv * gv.x + bv.x;
    float o1 = (xv.y - mu) * inv * gv.y + bv.y;
    float o2 = (xv.z - mu) * inv * gv.z + bv.z;
    float o3 = (xv.w - mu) * inv * gv.w + bv.w;

    if (outmode == 0) {
        *(float4*)&Yf[(size_t)row * D_ + t * 4] = make_float4(o0, o1, o2, o3);
    } else {
        __half2 h01 = __float22half2_rn(make_float2(o0, o1));
        __half2 h23 = __float22half2_rn(make_float2(o2, o3));
        __half2 l01 = __float22half2_rn(make_float2(
            o0 - __half2float(h01.x), o1 - __half2float(h01.y)));
        __half2 l23 = __float22half2_rn(make_float2(
            o2 - __half2float(h23.x), o3 - __half2float(h23.y)));
        *(__half2*)&Yhi[(size_t)row * D_ + t * 4]     = h01;
        *(__half2*)&Yhi[(size_t)row * D_ + t * 4 + 2] = h23;
        *(__half2*)&Ylo[(size_t)row * D_ + t * 4]     = l01;
        *(__half2*)&Ylo[(size_t)row * D_ + t * 4 + 2] = l23;
    }
}

// ============================================================
// launch plumbing
// ============================================================
constexpr size_t MB1 = 1024ull * 1024ull;
constexpr size_t OFF_QW = 0,       OFF_KW = 1*MB1,  OFF_VW = 2*MB1,  OFF_OW = 3*MB1;
constexpr size_t OFF_F1W1 = 4*MB1, OFF_F1W2 = 8*MB1;
constexpr size_t OFF_CQW = 12*MB1, OFF_CKW = 13*MB1, OFF_CVW = 14*MB1, OFF_COW = 15*MB1;
constexpr size_t OFF_F2W1 = 16*MB1, OFF_F2W2 = 20*MB1;

struct Ctx {
    __half *wt;
    __half *a_hi, *a_lo, *b_hi, *b_lo;
    __half *qhi, *qlo, *khi, *vhi;
    __half *yhi, *ylo;
    float *h2, *qkvb;
    uint32_t *bms, *bmc;
};

static inline void run_gemm(const __half* Ahi, const __half* Alo,
                            const Ctx& c, size_t woff, const float* bias,
                            float* Cf, __half* Chi, __half* Clo,
                            int M, int N, int K, int relu, int outmode, int terms,
                            SegOut so = SegOut{}) {
    dim3 grid(N / 128, M / 128), block(256);
    mma_gemm_kernel<<<grid, block, GEMM_SMEM>>>(
        Ahi, Alo, c.wt + woff, bias, Cf, Chi, Clo, so, M, N, K, relu, outmode, terms);
}
static inline void run_attn(const Ctx& c, const uint32_t* bm,
                            __half* ohi, int selfmode) {
    dim3 grid(B_ * H_, S_ / 64), block(128);
    mma_attn_kernel<<<grid, block, ATT_SMEM>>>(
        c.qhi, c.qlo, c.khi, c.vhi, bm, ohi, selfmode);
}

extern "C" void kernel_launch(void* const* d_in, const int* in_sizes, int n_in,
                              void* d_out, int out_size)
{
    (void)in_sizes; (void)n_in; (void)out_size;
    const float* x    = (const float*)d_in[0];
    const float* y    = (const float*)d_in[1];
    const int*   mask = (const int*)  d_in[2];
    const float* qw   = (const float*)d_in[3];
    const float* qb   = (const float*)d_in[4];
    const float* kw   = (const float*)d_in[5];
    const float* kb   = (const float*)d_in[6];
    const float* vw   = (const float*)d_in[7];
    const float* vb   = (const float*)d_in[8];
    const float* ow   = (const float*)d_in[9];
    const float* ob   = (const float*)d_in[10];
    const float* f1w1 = (const float*)d_in[11];
    const float* f1b1 = (const float*)d_in[12];
    const float* f1w2 = (const float*)d_in[13];
    const float* f1b2 = (const float*)d_in[14];
    const float* ln1g = (const float*)d_in[15];
    const float* ln1b = (const float*)d_in[16];
    const float* cqw  = (const float*)d_in[17];
    const float* ckw  = (const float*)d_in[18];
    const float* cvw  = (const float*)d_in[19];
    const float* cow  = (const float*)d_in[20];
    const float* cob  = (const float*)d_in[21];
    const float* f2w1 = (const float*)d_in[22];
    const float* f2b1 = (const float*)d_in[23];
    const float* f2w2 = (const float*)d_in[24];
    const float* f2b2 = (const float*)d_in[25];
    const float* ln2g = (const float*)d_in[26];
    const float* ln2b = (const float*)d_in[27];
    float* out = (float*)d_out;

    Ctx c;
    cudaGetSymbolAddress((void**)&c.wt,   g_wt);
    cudaGetSymbolAddress((void**)&c.a_hi, g_a_hi);
    cudaGetSymbolAddress((void**)&c.a_lo, g_a_lo);
    cudaGetSymbolAddress((void**)&c.b_hi, g_b_hi);
    cudaGetSymbolAddress((void**)&c.b_lo, g_b_lo);
    cudaGetSymbolAddress((void**)&c.qhi,  g_qhi);
    cudaGetSymbolAddress((void**)&c.qlo,  g_qlo);
    cudaGetSymbolAddress((void**)&c.khi,  g_khi);
    cudaGetSymbolAddress((void**)&c.vhi,  g_vhi);
    cudaGetSymbolAddress((void**)&c.yhi,  g_yhi);
    cudaGetSymbolAddress((void**)&c.ylo,  g_ylo);
    cudaGetSymbolAddress((void**)&c.h2,   g_h2);
    cudaGetSymbolAddress((void**)&c.qkvb, g_qkvb);
    cudaGetSymbolAddress((void**)&c.bms,  g_bms);
    cudaGetSymbolAddress((void**)&c.bmc,  g_bmc);

    cudaFuncSetAttribute(mma_gemm_kernel,
                         cudaFuncAttributeMaxDynamicSharedMemorySize, GEMM_SMEM);
    cudaFuncSetAttribute(mma_attn_kernel,
                         cudaFuncAttributeMaxDynamicSharedMemorySize, ATT_SMEM);

    // ---- prep: ONE launch ----
    {
        PrepAll p;
        const float* srcs[12] = { qw, kw, vw, ow, cqw, ckw, cvw, cow,
                                  f1w1, f2w1, f1w2, f2w2 };
        const size_t offs[12] = { OFF_QW, OFF_KW, OFF_VW, OFF_OW,
                                  OFF_CQW, OFF_CKW, OFF_CVW, OFF_COW,
                                  OFF_F1W1, OFF_F2W1, OFF_F1W2, OFF_F2W2 };
        for (int i = 0; i < 12; i++) { p.wsrc[i] = srcs[i]; p.wdst[i] = c.wt + offs[i]; }
        p.mask = mask; p.bms = c.bms; p.bmc = c.bmc;
        p.x = x; p.xhi = c.a_hi; p.xlo = c.a_lo;
        p.y = y; p.yhi = c.yhi; p.ylo = c.ylo;
        p.qb = qb; p.kb = kb; p.vb = vb; p.qkvb = c.qkvb;
        prep_all_kernel<<<21516, 256>>>(p);
    }

    // ---- self-attention: fused QKV projection (2-term) ----
    {
        SegOut so;
        so.hi[0] = c.qhi; so.hi[1] = c.khi; so.hi[2] = c.vhi;
        so.lo[0] = c.qlo; so.lo[1] = nullptr; so.lo[2] = nullptr;
        run_gemm(c.a_hi, c.a_lo, c, OFF_QW, c.qkvb, nullptr, nullptr, nullptr,
                 M_, 3 * D_, D_, 0, 3, 2, so);
    }
    run_attn(c, c.bms, c.b_hi, 1);
    // O-proj: A-side 1-term (attention output hi-only); hi-only output
    run_gemm(c.b_hi, c.b_hi, c, OFF_OW, ob, nullptr, c.a_hi, nullptr, M_, D_, D_, 0, 1, 1);

    // ---- feedforward1 + norm1 (FFN GEMMs 1-term) ----
    run_gemm(c.a_hi, c.a_hi, c, OFF_F1W1, f1b1, nullptr, c.b_hi, nullptr, M_, 4*D_, D_, 1, 1, 1);
    run_gemm(c.b_hi, c.b_hi, c, OFF_F1W2, f1b2, c.h2, nullptr, nullptr, M_, D_, 4*D_, 0, 0, 1);
    layernorm_kernel<<<M_, 256>>>(c.h2, ln1g, ln1b, nullptr, c.a_hi, c.a_lo, 1);

    // ---- cross-attention (2-term projections; y pre-split in prep) ----
    run_gemm(c.a_hi, c.a_lo, c, OFF_CQW, nullptr, nullptr, c.qhi, c.qlo, M_, D_, D_, 0, 1, 2);
    {
        SegOut so;
        so.hi[0] = c.khi; so.hi[1] = c.vhi; so.hi[2] = nullptr;
        so.lo[0] = nullptr; so.lo[1] = nullptr; so.lo[2] = nullptr;
        run_gemm(c.yhi, c.ylo, c, OFF_CKW, nullptr, nullptr, nullptr, nullptr,
                 M_, 2 * D_, D_, 0, 3, 2, so);
    }
    run_attn(c, c.bmc, c.b_hi, 0);
    // CO-proj: A-side 1-term; hi-only output
    run_gemm(c.b_hi, c.b_hi, c, OFF_COW, cob, nullptr, c.a_hi, nullptr, M_, D_, D_, 0, 1, 1);

    // ---- feedforward2 + norm2 (FFN GEMMs 1-term) ----
    run_gemm(c.a_hi, c.a_hi, c, OFF_F2W1, f2b1, nullptr, c.b_hi, nullptr, M_, 4*D_, D_, 1, 1, 1);
    run_gemm(c.b_hi, c.b_hi, c, OFF_F2W2, f2b2, c.h2, nullptr, nullptr, M_, D_, 4*D_, 0, 0, 1);
    layernorm_kernel<<<M_, 256>>>(c.h2, ln2g, ln2b, out, nullptr, nullptr, 0);
}

// round 17
// speedup vs baseline: 1.0335x; 1.0335x over previous
#include <cuda_runtime.h>
#include <cuda_fp16.h>
#include <math.h>
#include <stdint.h>

// ---------------- problem constants ----------------
constexpr int B_ = 2;
constexpr int S_ = 2048;
constexpr int D_ = 1024;
constexpr int H_ = 16;
constexpr int HD_ = 64;
constexpr int M_ = B_ * S_;          // 4096 rows
constexpr float LN_EPS = 1e-5f;
constexpr int BM_WORDS = M_ * S_ / 32;

// ---------------- device scratch (no allocations allowed) ----------------
__device__ float g_h2 [M_ * D_];
__device__ float g_qkvb[3 * D_];

constexpr size_t WT_ELEMS = 24ull * 1024 * 1024;
__device__ __half g_wt  [WT_ELEMS];                 // transposed fp16 weights
__device__ __half g_a_hi[M_ * 4 * D_];
__device__ __half g_a_lo[M_ * 4 * D_];
__device__ __half g_b_hi[M_ * 4 * D_];
__device__ __half g_b_lo[M_ * 4 * D_];
__device__ __half g_qhi[M_ * D_], g_qlo[M_ * D_];
__device__ __half g_khi[M_ * D_];
__device__ __half g_vhi[M_ * D_];
__device__ __half g_yhi[M_ * D_], g_ylo[M_ * D_];   // y split (prep-time)
__device__ uint32_t g_bms[BM_WORDS];
__device__ uint32_t g_bmc[BM_WORDS];

// ---------------- PTX helpers (sm_80-class only) ----------------
__device__ __forceinline__ uint32_t smem_to_u32(const void* smem_ptr) {
    uint32_t addr;
    asm("{ .reg .u64 tmp; cvta.to.shared.u64 tmp, %1; cvt.u32.u64 %0, tmp; }"
        : "=r"(addr) : "l"(smem_ptr));
    return addr;
}
#define CP_ASYNC16(dst_u32, src_ptr) \
    asm volatile("cp.async.cg.shared.global [%0], [%1], 16;" \
        :: "r"(dst_u32), "l"(src_ptr))
#define CP_COMMIT() asm volatile("cp.async.commit_group;" ::: "memory")
#define CP_WAIT0()  asm volatile("cp.async.wait_group 0;" ::: "memory")
#define CP_WAIT1()  asm volatile("cp.async.wait_group 1;" ::: "memory")
#define CP_WAIT2()  asm volatile("cp.async.wait_group 2;" ::: "memory")

#define LDSM_X4(r0, r1, r2, r3, addr) \
    asm volatile("ldmatrix.sync.aligned.m8n8.x4.shared.b16 {%0,%1,%2,%3}, [%4];" \
        : "=r"(r0), "=r"(r1), "=r"(r2), "=r"(r3) : "r"(addr))
#define LDSM_X4_T(r0, r1, r2, r3, addr) \
    asm volatile("ldmatrix.sync.aligned.m8n8.x4.trans.shared.b16 {%0,%1,%2,%3}, [%4];" \
        : "=r"(r0), "=r"(r1), "=r"(r2), "=r"(r3) : "r"(addr))

#define MMA_F16(c0, c1, c2, c3, a0, a1, a2, a3, b0, b1) \
    asm volatile("mma.sync.aligned.m16n8k16.row.col.f32.f16.f16.f32 " \
        "{%0,%1,%2,%3}, {%4,%5,%6,%7}, {%8,%9}, {%0,%1,%2,%3};" \
        : "+f"(c0), "+f"(c1), "+f"(c2), "+f"(c3) \
        : "r"(a0), "r"(a1), "r"(a2), "r"(a3), "r"(b0), "r"(b1))

__device__ __forceinline__ uint32_t h2u(__half2 v) {
    return *reinterpret_cast<uint32_t*>(&v);
}

// segmented-output descriptor: column segment s (1024 cols) -> hi[s]/lo[s]
struct SegOut { __half* hi[3]; __half* lo[3]; };

__device__ __forceinline__ uint32_t swz(uint32_t row, uint32_t gk) {
    return row * 64u + ((gk ^ ((row >> 1) & 3u)) << 4);
}

// ============================================================
// HMMA fp16 GEMM (2-term): C = (Ah+Al)[M,K] @ Wh[N,K]^T
// CTA 128x128, BK=32, 8 warps, 4-stage cp.async, 2 CTAs/SM.
// outmode 1: hi/lo Chi/Clo; 3: segmented SegOut
// ============================================================
constexpr int TILEB   = 8192;
constexpr int STAGEB  = 3 * TILEB;           // Ah, Al, Wh = 24KB
constexpr int GEMM_SMEM = 4 * STAGEB;        // 98304

__global__ __launch_bounds__(256, 2)
void mma_gemm_kernel(const __half* __restrict__ Ahi, const __half* __restrict__ Alo,
                     const __half* __restrict__ Wh,
                     const float* __restrict__ bias,
                     __half* __restrict__ Chi, __half* __restrict__ Clo,
                     SegOut so,
                     int M, int N, int K, int outmode)
{
    extern __shared__ char smem[];
    const uint32_t su = smem_to_u32(smem);
    const int tid  = threadIdx.x;
    const int wid  = tid >> 5;
    const int lane = tid & 31;
    const int block_row = blockIdx.y * 128;
    const int block_col = blockIdx.x * 128;

    const __half* basep[3] = { Ahi, Alo, Wh };
    const int rowoff[3] = { block_row, block_row, block_col };

    auto load_stage = [&](int p, int kt) {
        const int k0 = kt * 32;
        #pragma unroll
        for (int i = 0; i < 6; i++) {
            int lin  = tid + (i << 8);
            int tile = lin >> 9;
            int rem  = lin & 511;
            int row  = rem >> 2;
            int g    = rem & 3;
            const __half* src =
                basep[tile] + (size_t)(rowoff[tile] + row) * K + k0 + g * 8;
            uint32_t dst = su + p * STAGEB + tile * TILEB + swz(row, g);
            CP_ASYNC16(dst, src);
        }
    };

    float c[2][8][4];
    #pragma unroll
    for (int s = 0; s < 2; s++)
        #pragma unroll
        for (int n = 0; n < 8; n++)
            #pragma unroll
            for (int i = 0; i < 4; i++) c[s][n][i] = 0.f;

    const int wm = (wid & 3) * 32;
    const int wn = (wid >> 2) * 64;

    const int a_row  = (lane & 15);
    const int a_gsel = (lane >> 4);
    const int b_noff = ((lane >> 4) << 3) + (lane & 7);
    const int b_gsel = (lane >> 3) & 1;

    const int KT = K >> 5;
    load_stage(0, 0); CP_COMMIT();
    load_stage(1, 1); CP_COMMIT();
    load_stage(2, 2); CP_COMMIT();

    for (int kt = 0; kt < KT; kt++) {
        const int ahead = KT - 1 - kt;
        if (ahead >= 2)      CP_WAIT2();
        else if (ahead == 1) CP_WAIT1();
        else                 CP_WAIT0();
        __syncthreads();
        if (kt + 3 < KT) { load_stage((kt + 3) & 3, kt + 3); CP_COMMIT(); }

        const uint32_t stAhi = su + (kt & 3) * STAGEB;
        const uint32_t stAlo = stAhi + TILEB;
        const uint32_t stWh  = stAhi + 2 * TILEB;

        #pragma unroll
        for (int kk = 0; kk < 2; kk++) {
            uint32_t ah[2][4], al[2][4], bh[8][2];
            #pragma unroll
            for (int s = 0; s < 2; s++) {
                uint32_t ro = (uint32_t)(wm + s * 16 + a_row);
                uint32_t gk = (uint32_t)(kk * 2 + a_gsel);
                LDSM_X4(ah[s][0], ah[s][1], ah[s][2], ah[s][3], stAhi + swz(ro, gk));
                LDSM_X4(al[s][0], al[s][1], al[s][2], al[s][3], stAlo + swz(ro, gk));
            }
            #pragma unroll
            for (int grp = 0; grp < 4; grp++) {
                uint32_t ro = (uint32_t)(wn + grp * 16 + b_noff);
                uint32_t gk = (uint32_t)(kk * 2 + b_gsel);
                LDSM_X4(bh[2*grp][0], bh[2*grp][1], bh[2*grp+1][0], bh[2*grp+1][1],
                        stWh + swz(ro, gk));
            }
            #pragma unroll
            for (int s = 0; s < 2; s++)
                #pragma unroll
                for (int n = 0; n < 8; n++)
                    MMA_F16(c[s][n][0], c[s][n][1], c[s][n][2], c[s][n][3],
                            ah[s][0], ah[s][1], ah[s][2], ah[s][3],
                            bh[n][0], bh[n][1]);
            #pragma unroll
            for (int s = 0; s < 2; s++)
                #pragma unroll
                for (int n = 0; n < 8; n++)
                    MMA_F16(c[s][n][0], c[s][n][1], c[s][n][2], c[s][n][3],
                            al[s][0], al[s][1], al[s][2], al[s][3],
                            bh[n][0], bh[n][1]);
        }
    }

    const int seg = block_col >> 10;
    __half* seg_hi = (outmode == 3) ? so.hi[seg] : Chi;
    __half* seg_lo = (outmode == 3) ? so.lo[seg] : Clo;
    const int cstride = (outmode == 3) ? D_ : N;
    const int cmask = (outmode == 3) ? 1023 : 0x7fffffff;

    const int gp  = lane >> 2;
    const int tig = lane & 3;
    #pragma unroll
    for (int s = 0; s < 2; s++) {
        const int r0 = block_row + wm + s * 16 + gp;
        #pragma unroll
        for (int n = 0; n < 8; n++) {
            const int col = block_col + wn + n * 8 + tig * 2;
            float b0 = bias ? __ldg(&bias[col])     : 0.f;
            float b1 = bias ? __ldg(&bias[col + 1]) : 0.f;
            float v0 = c[s][n][0] + b0, v1 = c[s][n][1] + b1;
            float v2 = c[s][n][2] + b0, v3 = c[s][n][3] + b1;
            const int lc = col & cmask;
            __half2 h01 = __float22half2_rn(make_float2(v0, v1));
            __half2 h23 = __float22half2_rn(make_float2(v2, v3));
            *(__half2*)&seg_hi[(size_t)r0 * cstride + lc]       = h01;
            *(__half2*)&seg_hi[(size_t)(r0 + 8) * cstride + lc] = h23;
            if (seg_lo) {
                __half2 l01 = __float22half2_rn(make_float2(
                    v0 - __half2float(h01.x), v1 - __half2float(h01.y)));
                __half2 l23 = __float22half2_rn(make_float2(
                    v2 - __half2float(h23.x), v3 - __half2float(h23.y)));
                *(__half2*)&seg_lo[(size_t)r0 * cstride + lc]       = l01;
                *(__half2*)&seg_lo[(size_t)(r0 + 8) * cstride + lc] = l23;
            }
        }
    }
}

// ============================================================
// HMMA fp16 GEMM (1-term, paired stages): C = Ah[M,K] @ Wh[N,K]^T
// CTA 128x128, 6 stages of 16KB = 3 pair-slots (64 k per barrier).
// Half the barriers of the 2-term kernel; identical MMA order.
// outmode 0: fp32 Cf; 1: fp16 hi only. bias always present.
// ============================================================
constexpr int P1SLOT = 32768;                // pair slot: 2 x (A 8K + W 8K)
constexpr int GEMM1_SMEM = 3 * P1SLOT;       // 98304

__global__ __launch_bounds__(256, 2)
void mma_gemm1_kernel(const __half* __restrict__ Ahi, const __half* __restrict__ Wh,
                      const float* __restrict__ bias, float* __restrict__ Cf,
                      __half* __restrict__ Chi,
                      int M, int N, int K, int relu, int outmode)
{
    extern __shared__ char smem[];
    const uint32_t su = smem_to_u32(smem);
    const int tid  = threadIdx.x;
    const int wid  = tid >> 5;
    const int lane = tid & 31;
    const int block_row = blockIdx.y * 128;
    const int block_col = blockIdx.x * 128;

    auto load_ktile = [&](int slot, int sub, int kt) {
        const int k0 = kt * 32;
        #pragma unroll
        for (int i = 0; i < 4; i++) {
            int lin  = tid + (i << 8);          // 0..1023
            int tile = lin >> 9;                 // 0=A, 1=W
            int rem  = lin & 511;
            int row  = rem >> 2;
            int g    = rem & 3;
            const __half* src = (tile ? Wh + (size_t)(block_col + row) * K
                                      : Ahi + (size_t)(block_row + row) * K)
                                + k0 + g * 8;
            uint32_t dst = su + slot * P1SLOT + sub * 16384 + tile * 8192 + swz(row, g);
            CP_ASYNC16(dst, src);
        }
    };

    float c[2][8][4];
    #pragma unroll
    for (int s = 0; s < 2; s++)
        #pragma unroll
        for (int n = 0; n < 8; n++)
            #pragma unroll
            for (int i = 0; i < 4; i++) c[s][n][i] = 0.f;

    const int wm = (wid & 3) * 32;
    const int wn = (wid >> 2) * 64;

    const int a_row  = (lane & 15);
    const int a_gsel = (lane >> 4);
    const int b_noff = ((lane >> 4) << 3) + (lane & 7);
    const int b_gsel = (lane >> 3) & 1;

    const int NP = K >> 6;                   // pairs of k-tiles
    load_ktile(0, 0, 0); load_ktile(0, 1, 1); CP_COMMIT();
    load_ktile(1, 0, 2); load_ktile(1, 1, 3); CP_COMMIT();

    int slot = 0;
    for (int p = 0; p < NP; p++) {
        if (p + 1 < NP) CP_WAIT1();
        else            CP_WAIT0();
        __syncthreads();
        if (p + 2 < NP) {
            int ns = slot + 2; if (ns >= 3) ns -= 3;
            load_ktile(ns, 0, 2 * (p + 2));
            load_ktile(ns, 1, 2 * (p + 2) + 1);
            CP_COMMIT();
        }
        const uint32_t base = su + slot * P1SLOT;
        slot++; if (slot == 3) slot = 0;

        #pragma unroll
        for (int sub = 0; sub < 2; sub++) {
            const uint32_t stA = base + sub * 16384;
            const uint32_t stW = stA + 8192;
            #pragma unroll
            for (int kk = 0; kk < 2; kk++) {
                uint32_t ah[2][4], bh[8][2];
                #pragma unroll
                for (int s = 0; s < 2; s++) {
                    uint32_t ro = (uint32_t)(wm + s * 16 + a_row);
                    uint32_t gk = (uint32_t)(kk * 2 + a_gsel);
                    LDSM_X4(ah[s][0], ah[s][1], ah[s][2], ah[s][3], stA + swz(ro, gk));
                }
                #pragma unroll
                for (int grp = 0; grp < 4; grp++) {
                    uint32_t ro = (uint32_t)(wn + grp * 16 + b_noff);
                    uint32_t gk = (uint32_t)(kk * 2 + b_gsel);
                    LDSM_X4(bh[2*grp][0], bh[2*grp][1], bh[2*grp+1][0], bh[2*grp+1][1],
                            stW + swz(ro, gk));
                }
                #pragma unroll
                for (int s = 0; s < 2; s++)
                    #pragma unroll
                    for (int n = 0; n < 8; n++)
                        MMA_F16(c[s][n][0], c[s][n][1], c[s][n][2], c[s][n][3],
                                ah[s][0], ah[s][1], ah[s][2], ah[s][3],
                                bh[n][0], bh[n][1]);
            }
        }
    }

    const int gp  = lane >> 2;
    const int tig = lane & 3;
    #pragma unroll
    for (int s = 0; s < 2; s++) {
        const int r0 = block_row + wm + s * 16 + gp;
        #pragma unroll
        for (int n = 0; n < 8; n++) {
            const int col = block_col + wn + n * 8 + tig * 2;
            float b0 = __ldg(&bias[col]);
            float b1 = __ldg(&bias[col + 1]);
            float v0 = c[s][n][0] + b0, v1 = c[s][n][1] + b1;
            float v2 = c[s][n][2] + b0, v3 = c[s][n][3] + b1;
            if (relu) {
                v0 = fmaxf(v0, 0.f); v1 = fmaxf(v1, 0.f);
                v2 = fmaxf(v2, 0.f); v3 = fmaxf(v3, 0.f);
            }
            if (outmode == 0) {
                *(float2*)&Cf[(size_t)r0 * N + col]       = make_float2(v0, v1);
                *(float2*)&Cf[(size_t)(r0 + 8) * N + col] = make_float2(v2, v3);
            } else {
                __half2 h01 = __float22half2_rn(make_float2(v0, v1));
                __half2 h23 = __float22half2_rn(make_float2(v2, v3));
                *(__half2*)&Chi[(size_t)r0 * N + col]       = h01;
                *(__half2*)&Chi[(size_t)(r0 + 8) * N + col] = h23;
            }
        }
    }
}

// ============================================================
// MMA flash attention (fp16). QK: 2-term. PV: 1-term. Output hi
// only. CTA: 64 q-rows, 4 warps, Bc=64, bitmap mask, triple-buffer.
// ============================================================
constexpr int ATT_STAGE = 16384;
constexpr int ATT_SMEM  = 3 * ATT_STAGE;     // 49152

__device__ __forceinline__ uint32_t offKV(uint32_t row, uint32_t g) {
    return row * 128u + ((g ^ (row & 7u)) << 4);
}

__global__ __launch_bounds__(128, 4)
void mma_attn_kernel(const __half* __restrict__ Qhi, const __half* __restrict__ Qlo,
                     const __half* __restrict__ Khi, const __half* __restrict__ Vhi,
                     const uint32_t* __restrict__ bm,
                     __half* __restrict__ Ohi,
                     int selfmode)
{
    extern __shared__ char smem[];
    const uint32_t su = smem_to_u32(smem);
    const int tid = threadIdx.x, wid = tid >> 5, lane = tid & 31;
    const int b = blockIdx.x >> 4, h = blockIdx.x & 15;
    const int q0 = blockIdx.y * 64;

    #pragma unroll
    for (int i = 0; i < 8; i++) {
        int lin = tid + (i << 7);
        int t = lin >> 9, rem = lin & 511, row = rem >> 3, g = rem & 7;
        const __half* src = (t ? Qlo : Qhi) +
            ((size_t)b * S_ + q0 + row) * D_ + h * 64 + g * 8;
        CP_ASYNC16(su + t * 8192 + offKV(row, g), src);
    }
    CP_COMMIT(); CP_WAIT0(); __syncthreads();

    uint32_t qa_hi[4][4], qa_lo[4][4];
    {
        const uint32_t arow = (uint32_t)(wid * 16 + (lane & 15));
        const uint32_t ag = (uint32_t)(lane >> 4);
        #pragma unroll
        for (int kk = 0; kk < 4; kk++) {
            LDSM_X4(qa_hi[kk][0], qa_hi[kk][1], qa_hi[kk][2], qa_hi[kk][3],
                    su + offKV(arow, kk * 2 + ag));
            LDSM_X4(qa_lo[kk][0], qa_lo[kk][1], qa_lo[kk][2], qa_lo[kk][3],
                    su + 8192 + offKV(arow, kk * 2 + ag));
        }
    }
    __syncthreads();

    float o[8][4];
    #pragma unroll
    for (int n = 0; n < 8; n++)
        #pragma unroll
        for (int i = 0; i < 4; i++) o[n][i] = 0.f;
    float m0 = -INFINITY, m1 = -INFINITY, l0 = 0.f, l1 = 0.f;
    const float scale = 0.125f;
    const float bigneg = selfmode ? -3.0e38f : -1.25e8f;

    const int b_noff = ((lane >> 4) << 3) + (lane & 7);
    const int b_gsel = (lane >> 3) & 1;
    const int mr0 = wid * 16 + (lane >> 2);
    const int msh = (2 * (lane & 3));

    const __half* kvp[2] = { Khi, Vhi };
    const uint32_t* bmr0 = bm + ((size_t)b * S_ + q0 + mr0) * (S_ / 32);
    const uint32_t* bmr1 = bmr0 + 8 * (S_ / 32);

    auto load_kv = [&](int buf, int jt) {
        const int j0 = jt * 64;
        #pragma unroll
        for (int i = 0; i < 8; i++) {
            int lin = tid + (i << 7);
            int t = lin >> 9, rem = lin & 511, row = rem >> 3, g = rem & 7;
            CP_ASYNC16(su + buf * ATT_STAGE + t * 8192 + offKV(row, g),
                       kvp[t] + ((size_t)b * S_ + j0 + row) * D_ + h * 64 + g * 8);
        }
    };

    load_kv(0, 0); CP_COMMIT();
    load_kv(1, 1); CP_COMMIT();

    int buf = 0;
    for (int jt = 0; jt < 32; jt++) {
        const int ahead = 31 - jt;
        if (ahead >= 1) CP_WAIT1();
        else            CP_WAIT0();
        __syncthreads();
        if (jt + 2 < 32) {
            int nb = buf + 2; if (nb >= 3) nb -= 3;
            load_kv(nb, jt + 2); CP_COMMIT();
        }

        const uint32_t sb = su + buf * ATT_STAGE;
        buf++; if (buf == 3) buf = 0;

        const uint32_t u00 = __ldg(&bmr0[jt * 2]), u01 = __ldg(&bmr0[jt * 2 + 1]);
        const uint32_t u10 = __ldg(&bmr1[jt * 2]), u11 = __ldg(&bmr1[jt * 2 + 1]);

        float sc[8][4];
        #pragma unroll
        for (int n = 0; n < 8; n++)
            #pragma unroll
            for (int i = 0; i < 4; i++) sc[n][i] = 0.f;

        #pragma unroll
        for (int kk = 0; kk < 4; kk++) {
            uint32_t kbh[8][2];
            #pragma unroll
            for (int grp = 0; grp < 4; grp++) {
                uint32_t ro = (uint32_t)(grp * 16 + b_noff);
                uint32_t gd = (uint32_t)(kk * 2 + b_gsel);
                LDSM_X4(kbh[2*grp][0], kbh[2*grp][1], kbh[2*grp+1][0], kbh[2*grp+1][1],
                        sb + offKV(ro, gd));
            }
            #pragma unroll
            for (int n = 0; n < 8; n++)
                MMA_F16(sc[n][0], sc[n][1], sc[n][2], sc[n][3],
                        qa_hi[kk][0], qa_hi[kk][1], qa_hi[kk][2], qa_hi[kk][3],
                        kbh[n][0], kbh[n][1]);
            #pragma unroll
            for (int n = 0; n < 8; n++)
                MMA_F16(sc[n][0], sc[n][1], sc[n][2], sc[n][3],
                        qa_lo[kk][0], qa_lo[kk][1], qa_lo[kk][2], qa_lo[kk][3],
                        kbh[n][0], kbh[n][1]);
        }

        #pragma unroll
        for (int n = 0; n < 8; n++) {
            const uint32_t w0 = (n < 4) ? u00 : u01;
            const uint32_t w1 = (n < 4) ? u10 : u11;
            const int sh = ((n * 8) & 31) + msh;
            bool f0 = (w0 >> sh) & 1, f1 = (w0 >> (sh + 1)) & 1;
            bool f2 = (w1 >> sh) & 1, f3 = (w1 >> (sh + 1)) & 1;
            sc[n][0] = f0 ? bigneg : sc[n][0] * scale;
            sc[n][1] = f1 ? bigneg : sc[n][1] * scale;
            sc[n][2] = f2 ? bigneg : sc[n][2] * scale;
            sc[n][3] = f3 ? bigneg : sc[n][3] * scale;
        }

        float tm0 = -INFINITY, tm1 = -INFINITY;
        #pragma unroll
        for (int n = 0; n < 8; n++) {
            tm0 = fmaxf(tm0, fmaxf(sc[n][0], sc[n][1]));
            tm1 = fmaxf(tm1, fmaxf(sc[n][2], sc[n][3]));
        }
        tm0 = fmaxf(tm0, __shfl_xor_sync(0xffffffffu, tm0, 1));
        tm0 = fmaxf(tm0, __shfl_xor_sync(0xffffffffu, tm0, 2));
        tm1 = fmaxf(tm1, __shfl_xor_sync(0xffffffffu, tm1, 1));
        tm1 = fmaxf(tm1, __shfl_xor_sync(0xffffffffu, tm1, 2));
        float nm0 = fmaxf(m0, tm0), nm1 = fmaxf(m1, tm1);
        float c0 = __expf(m0 - nm0), c1 = __expf(m1 - nm1);
        m0 = nm0; m1 = nm1;

        float rs0 = 0.f, rs1 = 0.f;
        uint32_t pah[8][2];
        #pragma unroll
        for (int n = 0; n < 8; n++) {
            float p0 = __expf(sc[n][0] - m0);
            float p1 = __expf(sc[n][1] - m0);
            float p2 = __expf(sc[n][2] - m1);
            float p3 = __expf(sc[n][3] - m1);
            rs0 += p0 + p1; rs1 += p2 + p3;
            pah[n][0] = h2u(__float22half2_rn(make_float2(p0, p1)));
            pah[n][1] = h2u(__float22half2_rn(make_float2(p2, p3)));
        }
        rs0 += __shfl_xor_sync(0xffffffffu, rs0, 1);
        rs0 += __shfl_xor_sync(0xffffffffu, rs0, 2);
        rs1 += __shfl_xor_sync(0xffffffffu, rs1, 1);
        rs1 += __shfl_xor_sync(0xffffffffu, rs1, 2);
        l0 = l0 * c0 + rs0;
        l1 = l1 * c1 + rs1;
        #pragma unroll
        for (int n = 0; n < 8; n++) {
            o[n][0] *= c0; o[n][1] *= c0; o[n][2] *= c1; o[n][3] *= c1;
        }

        #pragma unroll
        for (int kk = 0; kk < 4; kk++) {
            uint32_t ah0 = pah[2*kk][0], ah1 = pah[2*kk][1];
            uint32_t ah2 = pah[2*kk+1][0], ah3 = pah[2*kk+1][1];
            uint32_t vrow = (uint32_t)(kk * 16 + (lane & 15));
            #pragma unroll
            for (int nbp = 0; nbp < 4; nbp++) {
                uint32_t vg = (uint32_t)(nbp * 2 + (lane >> 4));
                uint32_t vh0, vh1, vh2, vh3;
                LDSM_X4_T(vh0, vh1, vh2, vh3, sb + 8192 + offKV(vrow, vg));
                MMA_F16(o[2*nbp][0], o[2*nbp][1], o[2*nbp][2], o[2*nbp][3],
                        ah0, ah1, ah2, ah3, vh0, vh1);
                MMA_F16(o[2*nbp+1][0], o[2*nbp+1][1], o[2*nbp+1][2], o[2*nbp+1][3],
                        ah0, ah1, ah2, ah3, vh2, vh3);
            }
        }
    }

    const float i0 = 1.f / l0, i1 = 1.f / l1;
    const size_t gr0 = (size_t)b * S_ + q0 + wid * 16 + (lane >> 2);
    #pragma unroll
    for (int n = 0; n < 8; n++) {
        const int col = h * 64 + n * 8 + 2 * (lane & 3);
        __half2 h01 = __float22half2_rn(make_float2(o[n][0] * i0, o[n][1] * i0));
        __half2 h23 = __float22half2_rn(make_float2(o[n][2] * i1, o[n][3] * i1));
        *(__half2*)&Ohi[gr0 * D_ + col]       = h01;
        *(__half2*)&Ohi[(gr0 + 8) * D_ + col] = h23;
    }
}

// ============================================================
// unified prep kernel (one launch, proven)
// ============================================================
struct PrepAll {
    const float* wsrc[12]; __half* wdst[12];
    const int* mask; uint32_t* bms; uint32_t* bmc;
    const float* x; __half* xhi; __half* xlo;
    const float* y; __half* yhi; __half* ylo;
    const float* qb; const float* kb; const float* vb; float* qkvb;
};

__device__ __forceinline__ void asplit_elem(const float* A, __half* hi, __half* lo, int i)
{
    float4 v = ((const float4*)A)[i];
    __half2 h01 = __float22half2_rn(make_float2(v.x, v.y));
    __half2 h23 = __float22half2_rn(make_float2(v.z, v.w));
    __half2 l01 = __float22half2_rn(make_float2(
        v.x - __half2float(h01.x), v.y - __half2float(h01.y)));
    __half2 l23 = __float22half2_rn(make_float2(
        v.z - __half2float(h23.x), v.w - __half2float(h23.y)));
    ((__half2*)hi)[2 * i + 0] = h01;
    ((__half2*)hi)[2 * i + 1] = h23;
    ((__half2*)lo)[2 * i + 0] = l01;
    ((__half2*)lo)[2 * i + 1] = l23;
}

__global__ __launch_bounds__(256)
void prep_all_kernel(PrepAll p)
{
    __shared__ float t[64][33];
    const int bx = blockIdx.x;
    const int tid = threadIdx.x;

    if (bx < 12288) {
        int w, ntile, ktile, K, N;
        if (bx < 4096) {
            w = bx >> 9;
            int r = bx & 511;
            ntile = r & 31; ktile = r >> 5;
            K = 1024; N = 1024;
        } else if (bx < 8192) {
            int i = bx - 4096;
            w = 8 + (i >> 11);
            int r = i & 2047;
            ntile = r & 127; ktile = r >> 7;
            K = 1024; N = 4096;
        } else {
            int i = bx - 8192;
            w = 10 + (i >> 11);
            int r = i & 2047;
            ntile = r & 31; ktile = r >> 5;
            K = 4096; N = 1024;
        }
        const float* W = p.wsrc[w];
        __half* dst = p.wdst[w];
        const int n0 = ntile * 32, k0 = ktile * 64;
        #pragma unroll
        for (int i = 0; i < 8; i++) {
            int lin = tid + (i << 8);
            int kl = lin >> 5, nl = lin & 31;
            t[kl][nl] = W[(size_t)(k0 + kl) * N + n0 + nl];
        }
        __syncthreads();
        #pragma unroll
        for (int i = 0; i < 4; i++) {
            int lin = tid + (i << 8);
            int nr = lin >> 5, kc = lin & 31;
            __half2 v = __float22half2_rn(make_float2(t[2*kc][nr], t[2*kc+1][nr]));
            *(__half2*)&dst[(size_t)(n0 + nr) * K + k0 + 2*kc] = v;
        }
    } else if (bx < 13312) {
        const int lane = tid & 31;
        const size_t w = ((size_t)(bx - 12288) * 256 + tid) >> 5;
        const size_t base = w * 1024;
        #pragma unroll 4
        for (int i = 0; i < 32; i++) {
            int mv = p.mask[base + i * 32 + lane];
            uint32_t s = __ballot_sync(0xffffffffu, mv == 1);
            uint32_t c = __ballot_sync(0xffffffffu, mv != 0);
            if (lane == 0) { p.bms[w * 32 + i] = s; p.bmc[w * 32 + i] = c; }
        }
    } else if (bx < 17408) {
        int i = (bx - 13312) * 256 + tid;
        asplit_elem(p.x, p.xhi, p.xlo, i);
    } else if (bx < 21504) {
        int i = (bx - 17408) * 256 + tid;
        asplit_elem(p.y, p.yhi, p.ylo, i);
    } else {
        int i = (bx - 21504) * 256 + tid;
        if (i < 3 * D_)
            p.qkvb[i] = (i < D_) ? p.qb[i]
                       : (i < 2 * D_ ? p.kb[i - D_] : p.vb[i - 2 * D_]);
    }
}

// ============================================================
// LayerNorm
// ============================================================
__global__ __launch_bounds__(256)
void layernorm_kernel(const float* __restrict__ X, const float* __restrict__ gm,
                      const float* __restrict__ bt, float* __restrict__ Yf,
                      __half* __restrict__ Yhi, __half* __restrict__ Ylo,
                      int outmode)
{
    const int row = blockIdx.x;
    const int t = threadIdx.x;
    const float* x = X + (size_t)row * D_;

    float4 xv = *(const float4*)&x[t * 4];
    float s  = xv.x + xv.y + xv.z + xv.w;
    float ss = xv.x * xv.x + xv.y * xv.y + xv.z * xv.z + xv.w * xv.w;

    #pragma unroll
    for (int off = 16; off > 0; off >>= 1) {
        s  += __shfl_xor_sync(0xffffffffu, s, off);
        ss += __shfl_xor_sync(0xffffffffu, ss, off);
    }
    __shared__ float sbuf[8], ssbuf[8];
    if ((t & 31) == 0) { sbuf[t >> 5] = s; ssbuf[t >> 5] = ss; }
    __syncthreads();
    float ts = 0.f, tss = 0.f;
    #pragma unroll
    for (int i = 0; i < 8; i++) { ts += sbuf[i]; tss += ssbuf[i]; }

    const float invD = 1.f / (float)D_;
    float mu  = ts * invD;
    float var = tss * invD - mu * mu;
    float inv = rsqrtf(var + LN_EPS);

    float4 gv = *(const float4*)&gm[t * 4];
    float4 bv = *(const float4*)&bt[t * 4];
    float o0 = (xv.x - mu) * inv * gv.x + bv.x;
    float o1 = (xv.y - mu) * inv * gv.y + bv.y;
    float o2 = (xv.z - mu) * inv * gv.z + bv.z;
    float o3 = (xv.w - mu) * inv * gv.w + bv.w;

    if (outmode == 0) {
        *(float4*)&Yf[(size_t)row * D_ + t * 4] = make_float4(o0, o1, o2, o3);
    } else {
        __half2 h01 = __float22half2_rn(make_float2(o0, o1));
        __half2 h23 = __float22half2_rn(make_float2(o2, o3));
        __half2 l01 = __float22half2_rn(make_float2(
            o0 - __half2float(h01.x), o1 - __half2float(h01.y)));
        __half2 l23 = __float22half2_rn(make_float2(
            o2 - __half2float(h23.x), o3 - __half2float(h23.y)));
        *(__half2*)&Yhi[(size_t)row * D_ + t * 4]     = h01;
        *(__half2*)&Yhi[(size_t)row * D_ + t * 4 + 2] = h23;
        *(__half2*)&Ylo[(size_t)row * D_ + t * 4]     = l01;
        *(__half2*)&Ylo[(size_t)row * D_ + t * 4 + 2] = l23;
    }
}

// ============================================================
// launch plumbing
// ============================================================
constexpr size_t MB1 = 1024ull * 1024ull;
constexpr size_t OFF_QW = 0,       OFF_KW = 1*MB1,  OFF_VW = 2*MB1,  OFF_OW = 3*MB1;
constexpr size_t OFF_F1W1 = 4*MB1, OFF_F1W2 = 8*MB1;
constexpr size_t OFF_CQW = 12*MB1, OFF_CKW = 13*MB1, OFF_CVW = 14*MB1, OFF_COW = 15*MB1;
constexpr size_t OFF_F2W1 = 16*MB1, OFF_F2W2 = 20*MB1;

struct Ctx {
    __half *wt;
    __half *a_hi, *a_lo, *b_hi, *b_lo;
    __half *qhi, *qlo, *khi, *vhi;
    __half *yhi, *ylo;
    float *h2, *qkvb;
    uint32_t *bms, *bmc;
};

static inline void run_gemm2(const __half* Ahi, const __half* Alo,
                             const Ctx& c, size_t woff, const float* bias,
                             __half* Chi, __half* Clo,
                             int M, int N, int K, int outmode,
                             SegOut so = SegOut{}) {
    dim3 grid(N / 128, M / 128), block(256);
    mma_gemm_kernel<<<grid, block, GEMM_SMEM>>>(
        Ahi, Alo, c.wt + woff, bias, Chi, Clo, so, M, N, K, outmode);
}
static inline void run_gemm1(const __half* Ahi, const Ctx& c, size_t woff,
                             const float* bias, float* Cf, __half* Chi,
                             int M, int N, int K, int relu, int outmode) {
    dim3 grid(N / 128, M / 128), block(256);
    mma_gemm1_kernel<<<grid, block, GEMM1_SMEM>>>(
        Ahi, c.wt + woff, bias, Cf, Chi, M, N, K, relu, outmode);
}
static inline void run_attn(const Ctx& c, const uint32_t* bm,
                            __half* ohi, int selfmode) {
    dim3 grid(B_ * H_, S_ / 64), block(128);
    mma_attn_kernel<<<grid, block, ATT_SMEM>>>(
        c.qhi, c.qlo, c.khi, c.vhi, bm, ohi, selfmode);
}

extern "C" void kernel_launch(void* const* d_in, const int* in_sizes, int n_in,
                              void* d_out, int out_size)
{
    (void)in_sizes; (void)n_in; (void)out_size;
    const float* x    = (const float*)d_in[0];
    const float* y    = (const float*)d_in[1];
    const int*   mask = (const int*)  d_in[2];
    const float* qw   = (const float*)d_in[3];
    const float* qb   = (const float*)d_in[4];
    const float* kw   = (const float*)d_in[5];
    const float* kb   = (const float*)d_in[6];
    const float* vw   = (const float*)d_in[7];
    const float* vb   = (const float*)d_in[8];
    const float* ow   = (const float*)d_in[9];
    const float* ob   = (const float*)d_in[10];
    const float* f1w1 = (const float*)d_in[11];
    const float* f1b1 = (const float*)d_in[12];
    const float* f1w2 = (const float*)d_in[13];
    const float* f1b2 = (const float*)d_in[14];
    const float* ln1g = (const float*)d_in[15];
    const float* ln1b = (const float*)d_in[16];
    const float* cqw  = (const float*)d_in[17];
    const float* ckw  = (const float*)d_in[18];
    const float* cvw  = (const float*)d_in[19];
    const float* cow  = (const float*)d_in[20];
    const float* cob  = (const float*)d_in[21];
    const float* f2w1 = (const float*)d_in[22];
    const float* f2b1 = (const float*)d_in[23];
    const float* f2w2 = (const float*)d_in[24];
    const float* f2b2 = (const float*)d_in[25];
    const float* ln2g = (const float*)d_in[26];
    const float* ln2b = (const float*)d_in[27];
    float* out = (float*)d_out;

    Ctx c;
    cudaGetSymbolAddress((void**)&c.wt,   g_wt);
    cudaGetSymbolAddress((void**)&c.a_hi, g_a_hi);
    cudaGetSymbolAddress((void**)&c.a_lo, g_a_lo);
    cudaGetSymbolAddress((void**)&c.b_hi, g_b_hi);
    cudaGetSymbolAddress((void**)&c.b_lo, g_b_lo);
    cudaGetSymbolAddress((void**)&c.qhi,  g_qhi);
    cudaGetSymbolAddress((void**)&c.qlo,  g_qlo);
    cudaGetSymbolAddress((void**)&c.khi,  g_khi);
    cudaGetSymbolAddress((void**)&c.vhi,  g_vhi);
    cudaGetSymbolAddress((void**)&c.yhi,  g_yhi);
    cudaGetSymbolAddress((void**)&c.ylo,  g_ylo);
    cudaGetSymbolAddress((void**)&c.h2,   g_h2);
    cudaGetSymbolAddress((void**)&c.qkvb, g_qkvb);
    cudaGetSymbolAddress((void**)&c.bms,  g_bms);
    cudaGetSymbolAddress((void**)&c.bmc,  g_bmc);

    cudaFuncSetAttribute(mma_gemm_kernel,
                         cudaFuncAttributeMaxDynamicSharedMemorySize, GEMM_SMEM);
    cudaFuncSetAttribute(mma_gemm1_kernel,
                         cudaFuncAttributeMaxDynamicSharedMemorySize, GEMM1_SMEM);
    cudaFuncSetAttribute(mma_attn_kernel,
                         cudaFuncAttributeMaxDynamicSharedMemorySize, ATT_SMEM);

    // ---- prep: ONE launch ----
    {
        PrepAll p;
        const float* srcs[12] = { qw, kw, vw, ow, cqw, ckw, cvw, cow,
                                  f1w1, f2w1, f1w2, f2w2 };
        const size_t offs[12] = { OFF_QW, OFF_KW, OFF_VW, OFF_OW,
                                  OFF_CQW, OFF_CKW, OFF_CVW, OFF_COW,
                                  OFF_F1W1, OFF_F2W1, OFF_F1W2, OFF_F2W2 };
        for (int i = 0; i < 12; i++) { p.wsrc[i] = srcs[i]; p.wdst[i] = c.wt + offs[i]; }
        p.mask = mask; p.bms = c.bms; p.bmc = c.bmc;
        p.x = x; p.xhi = c.a_hi; p.xlo = c.a_lo;
        p.y = y; p.yhi = c.yhi; p.ylo = c.ylo;
        p.qb = qb; p.kb = kb; p.vb = vb; p.qkvb = c.qkvb;
        prep_all_kernel<<<21516, 256>>>(p);
    }

    // ---- self-attention: fused QKV projection (2-term) ----
    {
        SegOut so;
        so.hi[0] = c.qhi; so.hi[1] = c.khi; so.hi[2] = c.vhi;
        so.lo[0] = c.qlo; so.lo[1] = nullptr; so.lo[2] = nullptr;
        run_gemm2(c.a_hi, c.a_lo, c, OFF_QW, c.qkvb, nullptr, nullptr,
                  M_, 3 * D_, D_, 3, so);
    }
    run_attn(c, c.bms, c.b_hi, 1);
    // O-proj: 1-term paired-stage, hi-only output
    run_gemm1(c.b_hi, c, OFF_OW, ob, nullptr, c.a_hi, M_, D_, D_, 0, 1);

    // ---- feedforward1 + norm1 (1-term paired-stage) ----
    run_gemm1(c.a_hi, c, OFF_F1W1, f1b1, nullptr, c.b_hi, M_, 4*D_, D_, 1, 1);
    run_gemm1(c.b_hi, c, OFF_F1W2, f1b2, c.h2, nullptr, M_, D_, 4*D_, 0, 0);
    layernorm_kernel<<<M_, 256>>>(c.h2, ln1g, ln1b, nullptr, c.a_hi, c.a_lo, 1);

    // ---- cross-attention (2-term projections; y pre-split in prep) ----
    run_gemm2(c.a_hi, c.a_lo, c, OFF_CQW, nullptr, c.qhi, c.qlo, M_, D_, D_, 1);
    {
        SegOut so;
        so.hi[0] = c.khi; so.hi[1] = c.vhi; so.hi[2] = nullptr;
        so.lo[0] = nullptr; so.lo[1] = nullptr; so.lo[2] = nullptr;
        run_gemm2(c.yhi, c.ylo, c, OFF_CKW, nullptr, nullptr, nullptr,
                  M_, 2 * D_, D_, 3, so);
    }
    run_attn(c, c.bmc, c.b_hi, 0);
    // CO-proj: 1-term paired-stage, hi-only output
    run_gemm1(c.b_hi, c, OFF_COW, cob, nullptr, c.a_hi, M_, D_, D_, 0, 1);

    // ---- feedforward2 + norm2 (1-term paired-stage) ----
    run_gemm1(c.a_hi, c, OFF_F2W1, f2b1, nullptr, c.b_hi, M_, 4*D_, D_, 1, 1);
    run_gemm1(c.b_hi, c, OFF_F2W2, f2b2, c.h2, nullptr, M_, D_, 4*D_, 0, 0);
    layernorm_kernel<<<M_, 256>>>(c.h2, ln2g, ln2b, out, nullptr, nullptr, 0);
}